// round 1
// baseline (speedup 1.0000x reference)
#include <cuda_runtime.h>
#include <math.h>

// Problem constants
#define NN      20000
#define TT      60
#define DDIM    20
#define HH      128
#define GGDIM   128
#define NHEADS  4
#define CCH     32
#define EE      320000
#define ETOT    (EE + NN)
#define G4      512          // 4*H
#define KDIM    148          // D + H
#define LROWS   16
#define LKC     16

// ---------------- scratch (device globals; no allocation allowed) ------------
__device__ float g_Wt[KDIM * G4];       // transposed+packed LSTM weights [k][col]
__device__ float g_bsum[G4];            // bih + bhh
__device__ float g_h[NN * HH];
__device__ float g_c[NN * HH];
__device__ float g_xh[NN * GGDIM];
__device__ float g_agg[NN * GGDIM];
__device__ float g_feat[NN * GGDIM];    // layer outputs / layer-2 input
__device__ float g_asr[NN * NHEADS];
__device__ float g_adt[NN * NHEADS];
__device__ float g_emax[NN * NHEADS];
__device__ float g_denom[NN * NHEADS];
__device__ float g_ex[ETOT * NHEADS];

// ---------------- helpers ----------------------------------------------------
__device__ __forceinline__ float sigf(float x) { return 1.0f / (1.0f + expf(-x)); }

__device__ __forceinline__ void atomicMaxF(float* addr, float v) {
    v = v + 0.0f;                        // canonicalize -0 -> +0
    if (v >= 0.0f) atomicMax((int*)addr, __float_as_int(v));
    else           atomicMin((unsigned int*)addr, __float_as_uint(v));
}

// ---------------- one-time prep ----------------------------------------------
__global__ void prep_kernel(const float* __restrict__ Wih, const float* __restrict__ Whh,
                            const float* __restrict__ bih, const float* __restrict__ bhh) {
    int stride = gridDim.x * blockDim.x;
    for (int i = blockIdx.x * blockDim.x + threadIdx.x; i < KDIM * G4; i += stride) {
        int k = i / G4, col = i - k * G4;
        g_Wt[i] = (k < DDIM) ? Wih[col * DDIM + k] : Whh[col * HH + (k - DDIM)];
    }
    for (int i = blockIdx.x * blockDim.x + threadIdx.x; i < G4; i += stride)
        g_bsum[i] = bih[i] + bhh[i];
}

__global__ void zero_state_kernel() {
    int stride = gridDim.x * blockDim.x;
    for (int i = blockIdx.x * blockDim.x + threadIdx.x; i < NN * HH; i += stride) {
        g_h[i] = 0.0f;
        g_c[i] = 0.0f;
    }
}

// ---------------- LSTM step: gates = [xt|h] @ Wt + b, then cell update -------
__global__ __launch_bounds__(512) void lstm_step_kernel(const float* __restrict__ x, int t) {
    __shared__ float sW[LKC * G4];       // 32 KB, reused for gates in epilogue
    __shared__ float sA[LROWS * LKC];    // 1 KB
    const int tid = threadIdx.x;         // 0..511 = gate column
    const int n0  = blockIdx.x * LROWS;

    float acc[LROWS];
    const float bias = g_bsum[tid];
#pragma unroll
    for (int r = 0; r < LROWS; r++) acc[r] = bias;

    for (int kc0 = 0; kc0 < KDIM; kc0 += LKC) {
        const int kc = min(LKC, KDIM - kc0);
        __syncthreads();
        for (int i = tid; i < kc * G4; i += 512)
            sW[i] = g_Wt[kc0 * G4 + i];
        for (int i = tid; i < LROWS * kc; i += 512) {
            int r = i / kc, kk = i - r * kc;
            int k = kc0 + kk;
            int n = n0 + r;
            sA[r * LKC + kk] = (k < DDIM) ? x[n * (TT * DDIM) + t * DDIM + k]
                                          : g_h[n * HH + (k - DDIM)];
        }
        __syncthreads();
        if (kc == LKC) {
#pragma unroll
            for (int k = 0; k < LKC; k++) {
                float w = sW[k * G4 + tid];
#pragma unroll
                for (int r = 0; r < LROWS; r++)
                    acc[r] = fmaf(sA[r * LKC + k], w, acc[r]);
            }
        } else {
            for (int k = 0; k < kc; k++) {
                float w = sW[k * G4 + tid];
#pragma unroll
                for (int r = 0; r < LROWS; r++)
                    acc[r] = fmaf(sA[r * LKC + k], w, acc[r]);
            }
        }
    }

    __syncthreads();
#pragma unroll
    for (int r = 0; r < LROWS; r++) sW[r * G4 + tid] = acc[r];   // gates
    __syncthreads();

    for (int i = tid; i < LROWS * HH; i += 512) {
        int r = i >> 7, j = i & 127;
        float gi = sW[r * G4 + j];
        float gf = sW[r * G4 + HH + j];
        float gg = sW[r * G4 + 2 * HH + j];
        float go = sW[r * G4 + 3 * HH + j];
        int n = n0 + r;
        float cv = sigf(gf) * g_c[n * HH + j] + sigf(gi) * tanhf(gg);
        g_c[n * HH + j] = cv;
        g_h[n * HH + j] = sigf(go) * tanhf(cv);
    }
}

// ---------------- GAT: xh = X @ W ([N,128] @ [128,128]) ----------------------
__global__ __launch_bounds__(128) void gemm_xh_kernel(const float* __restrict__ W, int layer) {
    const float* __restrict__ X = (layer == 0) ? g_h : g_feat;
    __shared__ float sW[32 * GGDIM];     // 16 KB
    __shared__ float sA[32 * 32];        // 4 KB
    const int tid = threadIdx.x;         // output column
    const int n0  = blockIdx.x * 32;

    float acc[32];
#pragma unroll
    for (int r = 0; r < 32; r++) acc[r] = 0.0f;

    for (int k0 = 0; k0 < GGDIM; k0 += 32) {
        __syncthreads();
        for (int i = tid; i < 32 * GGDIM; i += 128) sW[i] = W[k0 * GGDIM + i];
        for (int i = tid; i < 32 * 32; i += 128) {
            int r = i >> 5, kk = i & 31;
            sA[i] = X[(n0 + r) * GGDIM + k0 + kk];
        }
        __syncthreads();
        for (int k = 0; k < 32; k++) {
            float w = sW[k * GGDIM + tid];
#pragma unroll
            for (int r = 0; r < 32; r++)
                acc[r] = fmaf(sA[r * 32 + k], w, acc[r]);
        }
    }
#pragma unroll
    for (int r = 0; r < 32; r++) g_xh[(n0 + r) * GGDIM + tid] = acc[r];
}

// ---------------- per-node attention scores ----------------------------------
__global__ void attn_kernel(const float* __restrict__ a_src, const float* __restrict__ a_dst) {
    int i = blockIdx.x * blockDim.x + threadIdx.x;
    if (i >= NN * NHEADS) return;
    int n = i >> 2, hd = i & 3;
    const float* xrow = g_xh + n * GGDIM + hd * CCH;
    float ss = 0.0f, sd = 0.0f;
#pragma unroll
    for (int c = 0; c < CCH; c++) {
        float v = xrow[c];
        ss = fmaf(v, a_src[hd * CCH + c], ss);
        sd = fmaf(v, a_dst[hd * CCH + c], sd);
    }
    g_asr[i] = ss;
    g_adt[i] = sd;
}

__global__ void fill_kernel() {
    int stride = gridDim.x * blockDim.x;
    for (int i = blockIdx.x * blockDim.x + threadIdx.x; i < NN * GGDIM; i += stride)
        g_agg[i] = 0.0f;
    for (int i = blockIdx.x * blockDim.x + threadIdx.x; i < NN * NHEADS; i += stride) {
        g_emax[i]  = -INFINITY;
        g_denom[i] = 0.0f;
    }
}

// ---------------- edge passes -------------------------------------------------
__global__ void edge_max_kernel(const int* __restrict__ ei) {
    int e = blockIdx.x * blockDim.x + threadIdx.x;
    if (e >= ETOT) return;
    int s, d;
    if (e < EE) { s = ei[e]; d = ei[EE + e]; } else { s = e - EE; d = s; }
#pragma unroll
    for (int hd = 0; hd < NHEADS; hd++) {
        float v = g_asr[s * NHEADS + hd] + g_adt[d * NHEADS + hd];
        v = (v > 0.0f) ? v : 0.2f * v;
        atomicMaxF(&g_emax[d * NHEADS + hd], v);
    }
}

__global__ void edge_exp_kernel(const int* __restrict__ ei) {
    int e = blockIdx.x * blockDim.x + threadIdx.x;
    if (e >= ETOT) return;
    int s, d;
    if (e < EE) { s = ei[e]; d = ei[EE + e]; } else { s = e - EE; d = s; }
#pragma unroll
    for (int hd = 0; hd < NHEADS; hd++) {
        float v = g_asr[s * NHEADS + hd] + g_adt[d * NHEADS + hd];
        v = (v > 0.0f) ? v : 0.2f * v;
        float ex = expf(v - g_emax[d * NHEADS + hd]);
        g_ex[e * NHEADS + hd] = ex;
        atomicAdd(&g_denom[d * NHEADS + hd], ex);
    }
}

__global__ void edge_agg_kernel(const int* __restrict__ ei) {
    int w    = (blockIdx.x * blockDim.x + threadIdx.x) >> 5;  // warp per edge
    int lane = threadIdx.x & 31;
    if (w >= ETOT) return;
    int s, d;
    if (w < EE) { s = ei[w]; d = ei[EE + w]; } else { s = w - EE; d = s; }
#pragma unroll
    for (int hd = 0; hd < NHEADS; hd++) {
        float alpha = g_ex[w * NHEADS + hd] / (g_denom[d * NHEADS + hd] + 1e-16f);
        int c = hd * CCH + lane;
        atomicAdd(&g_agg[d * GGDIM + c], alpha * g_xh[s * GGDIM + c]);
    }
}

__global__ void finalize_kernel(const float* __restrict__ bias) {
    int i = blockIdx.x * blockDim.x + threadIdx.x;
    if (i >= NN * GGDIM) return;
    float v = g_agg[i] + bias[i & (GGDIM - 1)];
    g_feat[i] = (v > 0.0f) ? v : (expf(v) - 1.0f);
}

// ---------------- linear head -------------------------------------------------
__global__ void head_kernel(const float* __restrict__ Wh, const float* __restrict__ bh,
                            float* __restrict__ out) {
    int n = blockIdx.x * blockDim.x + threadIdx.x;
    if (n >= NN) return;
    float a0 = bh[0], a1 = bh[1];
    const float* f = g_feat + n * GGDIM;
#pragma unroll 8
    for (int k = 0; k < GGDIM; k++) {
        float v = f[k];
        a0 = fmaf(v, Wh[2 * k + 0], a0);
        a1 = fmaf(v, Wh[2 * k + 1], a1);
    }
    out[2 * n + 0] = a0;
    out[2 * n + 1] = a1;
}

// ---------------- launch ------------------------------------------------------
extern "C" void kernel_launch(void* const* d_in, const int* in_sizes, int n_in,
                              void* d_out, int out_size) {
    const float* x_win  = (const float*)d_in[0];
    const int*   ei     = (const int*)  d_in[1];
    const float* Wih    = (const float*)d_in[2];
    const float* Whh    = (const float*)d_in[3];
    const float* bih    = (const float*)d_in[4];
    const float* bhh    = (const float*)d_in[5];
    const float* W1     = (const float*)d_in[6];
    const float* asrc1  = (const float*)d_in[7];
    const float* adst1  = (const float*)d_in[8];
    const float* b1     = (const float*)d_in[9];
    const float* W2     = (const float*)d_in[10];
    const float* asrc2  = (const float*)d_in[11];
    const float* adst2  = (const float*)d_in[12];
    const float* b2     = (const float*)d_in[13];
    const float* Wh     = (const float*)d_in[14];
    const float* bh     = (const float*)d_in[15];
    float* out = (float*)d_out;

    prep_kernel<<<128, 256>>>(Wih, Whh, bih, bhh);
    zero_state_kernel<<<1024, 256>>>();

    for (int t = 0; t < TT; t++)
        lstm_step_kernel<<<NN / LROWS, 512>>>(x_win, t);

    for (int layer = 0; layer < 2; layer++) {
        const float* W    = layer ? W2    : W1;
        const float* asrc = layer ? asrc2 : asrc1;
        const float* adst = layer ? adst2 : adst1;
        const float* bb   = layer ? b2    : b1;

        gemm_xh_kernel<<<NN / 32, 128>>>(W, layer);
        attn_kernel<<<(NN * NHEADS + 255) / 256, 256>>>(asrc, adst);
        fill_kernel<<<2048, 256>>>();
        edge_max_kernel<<<(ETOT + 255) / 256, 256>>>(ei);
        edge_exp_kernel<<<(ETOT + 255) / 256, 256>>>(ei);
        edge_agg_kernel<<<(ETOT * 32 + 255) / 256, 256>>>(ei);
        finalize_kernel<<<(NN * GGDIM + 255) / 256, 256>>>(bb);
    }

    head_kernel<<<(NN + 127) / 128, 128>>>(Wh, bh, out);
}

// round 2
// speedup vs baseline: 1.0752x; 1.0752x over previous
#include <cuda_runtime.h>
#include <math.h>

// Problem constants
#define NN      20000
#define TT      60
#define DDIM    20
#define HH      128
#define GGDIM   128
#define NHEADS  4
#define CCH     32
#define EE      320000
#define ETOT    (EE + NN)
#define G4      512          // 4*H
#define KDIM    148          // D + H
#define LROWS   16
#define LKC     16
#define SWP     516          // padded sW row stride (floats), mult of 4
#define SAP     20           // padded sA row stride (floats), mult of 4

// ---------------- scratch (device globals; no allocation allowed) ------------
__device__ float g_Wt[KDIM * G4];       // transposed+packed LSTM weights [k][col]
__device__ float g_bsum[G4];            // bih + bhh
__device__ float g_h[NN * HH];
__device__ float g_c[NN * HH];
__device__ float g_xh[NN * GGDIM];
__device__ float g_agg[NN * GGDIM];
__device__ float g_feat[NN * GGDIM];    // layer outputs / layer-2 input
__device__ float g_asr[NN * NHEADS];
__device__ float g_adt[NN * NHEADS];
__device__ float g_emax[NN * NHEADS];
__device__ float g_denom[NN * NHEADS];
__device__ float g_ex[ETOT * NHEADS];

// ---------------- helpers ----------------------------------------------------
__device__ __forceinline__ float sigf(float x) { return 1.0f / (1.0f + expf(-x)); }

__device__ __forceinline__ void atomicMaxF(float* addr, float v) {
    v = v + 0.0f;                        // canonicalize -0 -> +0
    if (v >= 0.0f) atomicMax((int*)addr, __float_as_int(v));
    else           atomicMin((unsigned int*)addr, __float_as_uint(v));
}

// ---------------- one-time prep ----------------------------------------------
__global__ void prep_kernel(const float* __restrict__ Wih, const float* __restrict__ Whh,
                            const float* __restrict__ bih, const float* __restrict__ bhh) {
    int stride = gridDim.x * blockDim.x;
    for (int i = blockIdx.x * blockDim.x + threadIdx.x; i < KDIM * G4; i += stride) {
        int k = i / G4, col = i - k * G4;
        g_Wt[i] = (k < DDIM) ? Wih[col * DDIM + k] : Whh[col * HH + (k - DDIM)];
    }
    for (int i = blockIdx.x * blockDim.x + threadIdx.x; i < G4; i += stride)
        g_bsum[i] = bih[i] + bhh[i];
}

__global__ void zero_state_kernel() {
    int stride = gridDim.x * blockDim.x;
    for (int i = blockIdx.x * blockDim.x + threadIdx.x; i < NN * HH; i += stride) {
        g_h[i] = 0.0f;
        g_c[i] = 0.0f;
    }
}

// ---------------- LSTM step: gates = [xt|h] @ Wt + b, then cell update -------
// Mainloop per k: 1 LDS.32 (weight) + 4 broadcast LDS.128 (activations) + 16 FFMA.
__global__ __launch_bounds__(512) void lstm_step_kernel(const float* __restrict__ x, int t) {
    __shared__ float sW[LKC * SWP];      // ~32.3 KB (weights tile, reused for gates)
    __shared__ float sAf[LKC * SAP];     // 1.25 KB (activations, transposed [k][r])
    const int tid = threadIdx.x;         // 0..511 = gate column
    const int n0  = blockIdx.x * LROWS;

    float acc[LROWS];
    const float bias = g_bsum[tid];
#pragma unroll
    for (int r = 0; r < LROWS; r++) acc[r] = bias;

    for (int kc0 = 0; kc0 < KDIM; kc0 += LKC) {
        const int kc = min(LKC, KDIM - kc0);
        __syncthreads();
        // weights: kc rows of 512 floats, vectorized copy into padded rows
        {
            const float4* __restrict__ src = (const float4*)(g_Wt + kc0 * G4);
            for (int i = tid; i < kc * (G4 / 4); i += 512) {
                int row = i >> 7, c4 = i & 127;
                *((float4*)(sW + row * SWP) + c4) = src[i];
            }
        }
        // activations: read gmem coalesced (k fast), store transposed [k][r]
        for (int i = tid; i < LROWS * kc; i += 512) {
            int r = i / kc, kk = i - r * kc;
            int k = kc0 + kk;
            int n = n0 + r;
            float v = (k < DDIM) ? x[n * (TT * DDIM) + t * DDIM + k]
                                 : g_h[n * HH + (k - DDIM)];
            sAf[kk * SAP + r] = v;
        }
        __syncthreads();
        if (kc == LKC) {
#pragma unroll
            for (int k = 0; k < LKC; k++) {
                float w = sW[k * SWP + tid];
                float4 a0 = *(const float4*)(sAf + k * SAP + 0);
                float4 a1 = *(const float4*)(sAf + k * SAP + 4);
                float4 a2 = *(const float4*)(sAf + k * SAP + 8);
                float4 a3 = *(const float4*)(sAf + k * SAP + 12);
                acc[0]  = fmaf(a0.x, w, acc[0]);
                acc[1]  = fmaf(a0.y, w, acc[1]);
                acc[2]  = fmaf(a0.z, w, acc[2]);
                acc[3]  = fmaf(a0.w, w, acc[3]);
                acc[4]  = fmaf(a1.x, w, acc[4]);
                acc[5]  = fmaf(a1.y, w, acc[5]);
                acc[6]  = fmaf(a1.z, w, acc[6]);
                acc[7]  = fmaf(a1.w, w, acc[7]);
                acc[8]  = fmaf(a2.x, w, acc[8]);
                acc[9]  = fmaf(a2.y, w, acc[9]);
                acc[10] = fmaf(a2.z, w, acc[10]);
                acc[11] = fmaf(a2.w, w, acc[11]);
                acc[12] = fmaf(a3.x, w, acc[12]);
                acc[13] = fmaf(a3.y, w, acc[13]);
                acc[14] = fmaf(a3.z, w, acc[14]);
                acc[15] = fmaf(a3.w, w, acc[15]);
            }
        } else {
            for (int k = 0; k < kc; k++) {
                float w = sW[k * SWP + tid];
                float4 a0 = *(const float4*)(sAf + k * SAP + 0);
                float4 a1 = *(const float4*)(sAf + k * SAP + 4);
                float4 a2 = *(const float4*)(sAf + k * SAP + 8);
                float4 a3 = *(const float4*)(sAf + k * SAP + 12);
                acc[0]  = fmaf(a0.x, w, acc[0]);
                acc[1]  = fmaf(a0.y, w, acc[1]);
                acc[2]  = fmaf(a0.z, w, acc[2]);
                acc[3]  = fmaf(a0.w, w, acc[3]);
                acc[4]  = fmaf(a1.x, w, acc[4]);
                acc[5]  = fmaf(a1.y, w, acc[5]);
                acc[6]  = fmaf(a1.z, w, acc[6]);
                acc[7]  = fmaf(a1.w, w, acc[7]);
                acc[8]  = fmaf(a2.x, w, acc[8]);
                acc[9]  = fmaf(a2.y, w, acc[9]);
                acc[10] = fmaf(a2.z, w, acc[10]);
                acc[11] = fmaf(a2.w, w, acc[11]);
                acc[12] = fmaf(a3.x, w, acc[12]);
                acc[13] = fmaf(a3.y, w, acc[13]);
                acc[14] = fmaf(a3.z, w, acc[14]);
                acc[15] = fmaf(a3.w, w, acc[15]);
            }
        }
    }

    __syncthreads();
#pragma unroll
    for (int r = 0; r < LROWS; r++) sW[r * SWP + tid] = acc[r];   // gates
    __syncthreads();

    for (int i = tid; i < LROWS * HH; i += 512) {
        int r = i >> 7, j = i & 127;
        float gi = sW[r * SWP + j];
        float gf = sW[r * SWP + HH + j];
        float gg = sW[r * SWP + 2 * HH + j];
        float go = sW[r * SWP + 3 * HH + j];
        int n = n0 + r;
        float cv = sigf(gf) * g_c[n * HH + j] + sigf(gi) * tanhf(gg);
        g_c[n * HH + j] = cv;
        g_h[n * HH + j] = sigf(go) * tanhf(cv);
    }
}

// ---------------- GAT: xh = X @ W ([N,128] @ [128,128]) ----------------------
__global__ __launch_bounds__(128) void gemm_xh_kernel(const float* __restrict__ W, int layer) {
    const float* __restrict__ X = (layer == 0) ? g_h : g_feat;
    __shared__ float sW[32 * GGDIM];     // 16 KB
    __shared__ float sA[32 * 32];        // 4 KB
    const int tid = threadIdx.x;         // output column
    const int n0  = blockIdx.x * 32;

    float acc[32];
#pragma unroll
    for (int r = 0; r < 32; r++) acc[r] = 0.0f;

    for (int k0 = 0; k0 < GGDIM; k0 += 32) {
        __syncthreads();
        for (int i = tid; i < 32 * GGDIM; i += 128) sW[i] = W[k0 * GGDIM + i];
        for (int i = tid; i < 32 * 32; i += 128) {
            int r = i >> 5, kk = i & 31;
            sA[i] = X[(n0 + r) * GGDIM + k0 + kk];
        }
        __syncthreads();
        for (int k = 0; k < 32; k++) {
            float w = sW[k * GGDIM + tid];
#pragma unroll
            for (int r = 0; r < 32; r++)
                acc[r] = fmaf(sA[r * 32 + k], w, acc[r]);
        }
    }
#pragma unroll
    for (int r = 0; r < 32; r++) g_xh[(n0 + r) * GGDIM + tid] = acc[r];
}

// ---------------- per-node attention scores ----------------------------------
__global__ void attn_kernel(const float* __restrict__ a_src, const float* __restrict__ a_dst) {
    int i = blockIdx.x * blockDim.x + threadIdx.x;
    if (i >= NN * NHEADS) return;
    int n = i >> 2, hd = i & 3;
    const float* xrow = g_xh + n * GGDIM + hd * CCH;
    float ss = 0.0f, sd = 0.0f;
#pragma unroll
    for (int c = 0; c < CCH; c++) {
        float v = xrow[c];
        ss = fmaf(v, a_src[hd * CCH + c], ss);
        sd = fmaf(v, a_dst[hd * CCH + c], sd);
    }
    g_asr[i] = ss;
    g_adt[i] = sd;
}

__global__ void fill_kernel() {
    int stride = gridDim.x * blockDim.x;
    for (int i = blockIdx.x * blockDim.x + threadIdx.x; i < NN * GGDIM; i += stride)
        g_agg[i] = 0.0f;
    for (int i = blockIdx.x * blockDim.x + threadIdx.x; i < NN * NHEADS; i += stride) {
        g_emax[i]  = -INFINITY;
        g_denom[i] = 0.0f;
    }
}

// ---------------- edge passes -------------------------------------------------
__global__ void edge_max_kernel(const int* __restrict__ ei) {
    int e = blockIdx.x * blockDim.x + threadIdx.x;
    if (e >= ETOT) return;
    int s, d;
    if (e < EE) { s = ei[e]; d = ei[EE + e]; } else { s = e - EE; d = s; }
#pragma unroll
    for (int hd = 0; hd < NHEADS; hd++) {
        float v = g_asr[s * NHEADS + hd] + g_adt[d * NHEADS + hd];
        v = (v > 0.0f) ? v : 0.2f * v;
        atomicMaxF(&g_emax[d * NHEADS + hd], v);
    }
}

__global__ void edge_exp_kernel(const int* __restrict__ ei) {
    int e = blockIdx.x * blockDim.x + threadIdx.x;
    if (e >= ETOT) return;
    int s, d;
    if (e < EE) { s = ei[e]; d = ei[EE + e]; } else { s = e - EE; d = s; }
#pragma unroll
    for (int hd = 0; hd < NHEADS; hd++) {
        float v = g_asr[s * NHEADS + hd] + g_adt[d * NHEADS + hd];
        v = (v > 0.0f) ? v : 0.2f * v;
        float ex = expf(v - g_emax[d * NHEADS + hd]);
        g_ex[e * NHEADS + hd] = ex;
        atomicAdd(&g_denom[d * NHEADS + hd], ex);
    }
}

__global__ void edge_agg_kernel(const int* __restrict__ ei) {
    int w    = (blockIdx.x * blockDim.x + threadIdx.x) >> 5;  // warp per edge
    int lane = threadIdx.x & 31;
    if (w >= ETOT) return;
    int s, d;
    if (w < EE) { s = ei[w]; d = ei[EE + w]; } else { s = w - EE; d = s; }
#pragma unroll
    for (int hd = 0; hd < NHEADS; hd++) {
        float alpha = g_ex[w * NHEADS + hd] / (g_denom[d * NHEADS + hd] + 1e-16f);
        int c = hd * CCH + lane;
        atomicAdd(&g_agg[d * GGDIM + c], alpha * g_xh[s * GGDIM + c]);
    }
}

__global__ void finalize_kernel(const float* __restrict__ bias) {
    int i = blockIdx.x * blockDim.x + threadIdx.x;
    if (i >= NN * GGDIM) return;
    float v = g_agg[i] + bias[i & (GGDIM - 1)];
    g_feat[i] = (v > 0.0f) ? v : (expf(v) - 1.0f);
}

// ---------------- linear head -------------------------------------------------
__global__ void head_kernel(const float* __restrict__ Wh, const float* __restrict__ bh,
                            float* __restrict__ out) {
    int n = blockIdx.x * blockDim.x + threadIdx.x;
    if (n >= NN) return;
    float a0 = bh[0], a1 = bh[1];
    const float* f = g_feat + n * GGDIM;
#pragma unroll 8
    for (int k = 0; k < GGDIM; k++) {
        float v = f[k];
        a0 = fmaf(v, Wh[2 * k + 0], a0);
        a1 = fmaf(v, Wh[2 * k + 1], a1);
    }
    out[2 * n + 0] = a0;
    out[2 * n + 1] = a1;
}

// ---------------- launch ------------------------------------------------------
extern "C" void kernel_launch(void* const* d_in, const int* in_sizes, int n_in,
                              void* d_out, int out_size) {
    const float* x_win  = (const float*)d_in[0];
    const int*   ei     = (const int*)  d_in[1];
    const float* Wih    = (const float*)d_in[2];
    const float* Whh    = (const float*)d_in[3];
    const float* bih    = (const float*)d_in[4];
    const float* bhh    = (const float*)d_in[5];
    const float* W1     = (const float*)d_in[6];
    const float* asrc1  = (const float*)d_in[7];
    const float* adst1  = (const float*)d_in[8];
    const float* b1     = (const float*)d_in[9];
    const float* W2     = (const float*)d_in[10];
    const float* asrc2  = (const float*)d_in[11];
    const float* adst2  = (const float*)d_in[12];
    const float* b2     = (const float*)d_in[13];
    const float* Wh     = (const float*)d_in[14];
    const float* bh     = (const float*)d_in[15];
    float* out = (float*)d_out;

    prep_kernel<<<128, 256>>>(Wih, Whh, bih, bhh);
    zero_state_kernel<<<1024, 256>>>();

    for (int t = 0; t < TT; t++)
        lstm_step_kernel<<<NN / LROWS, 512>>>(x_win, t);

    for (int layer = 0; layer < 2; layer++) {
        const float* W    = layer ? W2    : W1;
        const float* asrc = layer ? asrc2 : asrc1;
        const float* adst = layer ? adst2 : adst1;
        const float* bb   = layer ? b2    : b1;

        gemm_xh_kernel<<<NN / 32, 128>>>(W, layer);
        attn_kernel<<<(NN * NHEADS + 255) / 256, 256>>>(asrc, adst);
        fill_kernel<<<2048, 256>>>();
        edge_max_kernel<<<(ETOT + 255) / 256, 256>>>(ei);
        edge_exp_kernel<<<(ETOT + 255) / 256, 256>>>(ei);
        edge_agg_kernel<<<(ETOT * 32 + 255) / 256, 256>>>(ei);
        finalize_kernel<<<(NN * GGDIM + 255) / 256, 256>>>(bb);
    }

    head_kernel<<<(NN + 127) / 128, 128>>>(Wh, bh, out);
}

// round 4
// speedup vs baseline: 5.0424x; 4.6899x over previous
#include <cuda_runtime.h>
#include <cuda_fp16.h>
#include <math.h>
#include <stdint.h>

// ---------------- problem constants ------------------------------------------
#define NN      20000
#define TT      60
#define DDIM    20
#define HH      128
#define GGDIM   128
#define NHEADS  4
#define CCH     32
#define EE      320000
#define ETOT    (EE + NN)
#define G4      512                 // 4*H gate columns
#define LNODES  128                 // nodes per LSTM block (MMA M)
#define LGRID   157                 // 157*128 = 20096 >= 20000
#define GSTR    (LGRID * LNODES)    // padded node stride

#define KXP     40                  // A_x/W_x row stride in halves (logical K=32)
#define KHP     136                 // A_h/W_h row stride in halves (logical K=128)

// ---------------- LSTM smem layout (bytes) -----------------------------------
#define OFF_WX   0                          // 512 x KXP f16  (40960)
#define OFF_WH   40960                      // 512 x KHP f16  (139264)
#define OFF_AX   180224                     // 128 x KXP f16  (10240)
#define OFF_AH   190464                     // 128 x KHP f16  (34816)
#define OFF_BIAS 225280                     // 512 f32        (2048)
#define SMEM_TOTAL 227328

// ---------------- scratch (device globals; no allocation allowed) ------------
__device__ float g_h[GSTR * HH];
__device__ float g_xh[NN * GGDIM];
__device__ float g_agg[NN * GGDIM];
__device__ float g_feat[NN * GGDIM];
__device__ float g_asr[NN * NHEADS];
__device__ float g_adt[NN * NHEADS];
__device__ float g_emax[NN * NHEADS];
__device__ float g_denom[NN * NHEADS];
__device__ float g_ex[ETOT * NHEADS];

// ---------------- helpers -----------------------------------------------------
__device__ __forceinline__ float tanhapx(float x) {
    float y; asm("tanh.approx.f32 %0, %1;" : "=f"(y) : "f"(x)); return y;
}
__device__ __forceinline__ float sigt(float x) {      // sigmoid via tanh
    return fmaf(tanhapx(0.5f * x), 0.5f, 0.5f);
}
__device__ __forceinline__ void mma16816(float* d,
                                         uint32_t a0, uint32_t a1, uint32_t a2, uint32_t a3,
                                         uint32_t b0, uint32_t b1) {
    asm volatile(
        "mma.sync.aligned.m16n8k16.row.col.f32.f16.f16.f32 "
        "{%0,%1,%2,%3}, {%4,%5,%6,%7}, {%8,%9}, {%0,%1,%2,%3};"
        : "+f"(d[0]), "+f"(d[1]), "+f"(d[2]), "+f"(d[3])
        : "r"(a0), "r"(a1), "r"(a2), "r"(a3), "r"(b0), "r"(b1));
}

// ---------------- persistent LSTM kernel (all 60 steps, HMMA) -----------------
__global__ __launch_bounds__(256, 1) void lstm_all_kernel(
    const float* __restrict__ x,
    const float* __restrict__ Wih, const float* __restrict__ Whh,
    const float* __restrict__ bih, const float* __restrict__ bhh)
{
    extern __shared__ char smem[];
    __half* WX = (__half*)(smem + OFF_WX);
    __half* WH = (__half*)(smem + OFF_WH);
    __half* AX = (__half*)(smem + OFF_AX);
    __half* AH = (__half*)(smem + OFF_AH);
    float*  sbias = (float*)(smem + OFF_BIAS);

    const int tid = threadIdx.x;
    const int blk = blockIdx.x;

    // zero all padded f16 regions once
    for (int i = tid; i < (40960 + 139264) / 4; i += 256) ((uint32_t*)(smem + OFF_WX))[i] = 0;
    for (int i = tid; i < (10240 + 34816) / 4;  i += 256) ((uint32_t*)(smem + OFF_AX))[i] = 0;
    __syncthreads();

    // load weights, permuted so gate column n' = 4*j + gate  (orig row = gate*128 + j)
    for (int i = tid; i < G4 * DDIM; i += 256) {
        int n = i / DDIM, k = i - n * DDIM;
        int row = (n & 3) * HH + (n >> 2);
        WX[n * KXP + k] = __float2half_rn(Wih[row * DDIM + k]);
    }
    for (int i = tid; i < G4 * HH; i += 256) {
        int n = i >> 7, k = i & 127;
        int row = (n & 3) * HH + (n >> 2);
        WH[n * KHP + k] = __float2half_rn(Whh[row * HH + k]);
    }
    for (int i = tid; i < G4; i += 256) {
        int row = (i & 3) * HH + (i >> 2);
        sbias[i] = bih[row] + bhh[row];
    }
    __syncthreads();

    const int wid  = tid >> 5;
    const int lane = tid & 31;
    const int g    = lane >> 2;          // fragment group
    const int cc   = lane & 3;           // fragment thread-in-group
    const int n0   = wid * 64;           // warp's gate-column base
    const bool odd = (lane & 1);
    const int jbase = (n0 >> 2) + (cc >> 1);

    float bias0[8], bias1[8];
#pragma unroll
    for (int nt = 0; nt < 8; ++nt) {
        bias0[nt] = sbias[n0 + nt * 8 + 2 * cc];
        bias1[nt] = sbias[n0 + nt * 8 + 2 * cc + 1];
    }

    float creg[8][8];                    // cell state, register-resident
#pragma unroll
    for (int mt = 0; mt < 8; ++mt)
#pragma unroll
        for (int nt = 0; nt < 8; ++nt) creg[mt][nt] = 0.0f;

    for (int s = 0; s < TT; ++s) {
        // refill A_x for this timestep
        for (int i = tid; i < LNODES * DDIM; i += 256) {
            int mm = i / DDIM, k = i - mm * DDIM;
            int n = blk * LNODES + mm;
            AX[mm * KXP + k] = __float2half_rn(n < NN ? x[n * (TT * DDIM) + s * DDIM + k] : 0.0f);
        }
        __syncthreads();
        const bool last = (s == TT - 1);

#pragma unroll
        for (int mt = 0; mt < 8; ++mt) {
            float acc[8][4];
#pragma unroll
            for (int nt = 0; nt < 8; ++nt) {
                acc[nt][0] = bias0[nt]; acc[nt][1] = bias1[nt];
                acc[nt][2] = bias0[nt]; acc[nt][3] = bias1[nt];
            }
            // ---- x-part GEMM: K = 32 (2 k-steps) ----
            for (int ks = 0; ks < 2; ++ks) {
                const int k0 = ks * 16;
                const __half* ar = AX + (mt * 16 + g) * KXP + k0 + 2 * cc;
                uint32_t a0 = *(const uint32_t*)ar;
                uint32_t a1 = *(const uint32_t*)(ar + 8 * KXP);
                uint32_t a2 = *(const uint32_t*)(ar + 8);
                uint32_t a3 = *(const uint32_t*)(ar + 8 * KXP + 8);
#pragma unroll
                for (int nt = 0; nt < 8; ++nt) {
                    const __half* br = WX + (n0 + nt * 8 + g) * KXP + k0 + 2 * cc;
                    uint32_t b0 = *(const uint32_t*)br;
                    uint32_t b1 = *(const uint32_t*)(br + 8);
                    mma16816(acc[nt], a0, a1, a2, a3, b0, b1);
                }
            }
            // ---- h-part GEMM: K = 128 (8 k-steps) ----
            for (int ks = 0; ks < 8; ++ks) {
                const int k0 = ks * 16;
                const __half* ar = AH + (mt * 16 + g) * KHP + k0 + 2 * cc;
                uint32_t a0 = *(const uint32_t*)ar;
                uint32_t a1 = *(const uint32_t*)(ar + 8 * KHP);
                uint32_t a2 = *(const uint32_t*)(ar + 8);
                uint32_t a3 = *(const uint32_t*)(ar + 8 * KHP + 8);
#pragma unroll
                for (int nt = 0; nt < 8; ++nt) {
                    const __half* br = WH + (n0 + nt * 8 + g) * KHP + k0 + 2 * cc;
                    uint32_t b0 = *(const uint32_t*)br;
                    uint32_t b1 = *(const uint32_t*)(br + 8);
                    mma16816(acc[nt], a0, a1, a2, a3, b0, b1);
                }
            }

            __syncthreads();             // all warps done reading A_h rows of this m-tile

            // ---- epilogue for this m-tile (writes h_s into A_h rows mt*16..+15) ----
#pragma unroll
            for (int nt = 0; nt < 8; ++nt) {
                float c0 = acc[nt][0], c1 = acc[nt][1], c2 = acc[nt][2], c3 = acc[nt][3];
                float x0 = __shfl_xor_sync(0xffffffffu, c0, 1);
                float x1 = __shfl_xor_sync(0xffffffffu, c1, 1);
                float x2 = __shfl_xor_sync(0xffffffffu, c2, 1);
                float x3 = __shfl_xor_sync(0xffffffffu, c3, 1);
                float gi, gf, gg, go; int row;
                if (!odd) { gi = c0; gf = c1; gg = x0; go = x1; row = mt * 16 + g; }
                else      { gi = x2; gf = x3; gg = c2; go = c3; row = mt * 16 + g + 8; }
                int j = jbase + nt * 2;
                float cold = creg[mt][nt];
                float cn = sigt(gf) * cold + sigt(gi) * tanhapx(gg);
                creg[mt][nt] = cn;
                float hv = sigt(go) * tanhapx(cn);
                AH[row * KHP + j] = __float2half_rn(hv);
                if (last) g_h[(blk * LNODES + row) * HH + j] = hv;
            }
        }
        __syncthreads();
    }
}

// ---------------- GAT section (unchanged structure) ---------------------------
__device__ __forceinline__ void atomicMaxF(float* addr, float v) {
    v = v + 0.0f;
    if (v >= 0.0f) atomicMax((int*)addr, __float_as_int(v));
    else           atomicMin((unsigned int*)addr, __float_as_uint(v));
}

__global__ __launch_bounds__(128) void gemm_xh_kernel(const float* __restrict__ W, int layer) {
    const float* __restrict__ X = (layer == 0) ? g_h : g_feat;
    __shared__ float sW[32 * GGDIM];
    __shared__ float sA[32 * 32];
    const int tid = threadIdx.x;
    const int n0  = blockIdx.x * 32;

    float acc[32];
#pragma unroll
    for (int r = 0; r < 32; r++) acc[r] = 0.0f;

    for (int k0 = 0; k0 < GGDIM; k0 += 32) {
        __syncthreads();
        for (int i = tid; i < 32 * GGDIM; i += 128) sW[i] = W[k0 * GGDIM + i];
        for (int i = tid; i < 32 * 32; i += 128) {
            int r = i >> 5, kk = i & 31;
            sA[i] = X[(n0 + r) * GGDIM + k0 + kk];
        }
        __syncthreads();
        for (int k = 0; k < 32; k++) {
            float wv = sW[k * GGDIM + tid];
#pragma unroll
            for (int r = 0; r < 32; r++)
                acc[r] = fmaf(sA[r * 32 + k], wv, acc[r]);
        }
    }
#pragma unroll
    for (int r = 0; r < 32; r++) g_xh[(n0 + r) * GGDIM + tid] = acc[r];
}

__global__ void attn_kernel(const float* __restrict__ a_src, const float* __restrict__ a_dst) {
    int i = blockIdx.x * blockDim.x + threadIdx.x;
    if (i >= NN * NHEADS) return;
    int n = i >> 2, hd = i & 3;
    const float* xrow = g_xh + n * GGDIM + hd * CCH;
    float ss = 0.0f, sd = 0.0f;
#pragma unroll
    for (int c = 0; c < CCH; c++) {
        float v = xrow[c];
        ss = fmaf(v, a_src[hd * CCH + c], ss);
        sd = fmaf(v, a_dst[hd * CCH + c], sd);
    }
    g_asr[i] = ss;
    g_adt[i] = sd;
}

__global__ void fill_kernel() {
    int stride = gridDim.x * blockDim.x;
    for (int i = blockIdx.x * blockDim.x + threadIdx.x; i < NN * GGDIM; i += stride)
        g_agg[i] = 0.0f;
    for (int i = blockIdx.x * blockDim.x + threadIdx.x; i < NN * NHEADS; i += stride) {
        g_emax[i]  = -INFINITY;
        g_denom[i] = 0.0f;
    }
}

__global__ void edge_max_kernel(const int* __restrict__ ei) {
    int e = blockIdx.x * blockDim.x + threadIdx.x;
    if (e >= ETOT) return;
    int s, d;
    if (e < EE) { s = ei[e]; d = ei[EE + e]; } else { s = e - EE; d = s; }
#pragma unroll
    for (int hd = 0; hd < NHEADS; hd++) {
        float v = g_asr[s * NHEADS + hd] + g_adt[d * NHEADS + hd];
        v = (v > 0.0f) ? v : 0.2f * v;
        atomicMaxF(&g_emax[d * NHEADS + hd], v);
    }
}

__global__ void edge_exp_kernel(const int* __restrict__ ei) {
    int e = blockIdx.x * blockDim.x + threadIdx.x;
    if (e >= ETOT) return;
    int s, d;
    if (e < EE) { s = ei[e]; d = ei[EE + e]; } else { s = e - EE; d = s; }
#pragma unroll
    for (int hd = 0; hd < NHEADS; hd++) {
        float v = g_asr[s * NHEADS + hd] + g_adt[d * NHEADS + hd];
        v = (v > 0.0f) ? v : 0.2f * v;
        float ex = expf(v - g_emax[d * NHEADS + hd]);
        g_ex[e * NHEADS + hd] = ex;
        atomicAdd(&g_denom[d * NHEADS + hd], ex);
    }
}

__global__ void edge_agg_kernel(const int* __restrict__ ei) {
    int wv   = (blockIdx.x * blockDim.x + threadIdx.x) >> 5;
    int lane = threadIdx.x & 31;
    if (wv >= ETOT) return;
    int s, d;
    if (wv < EE) { s = ei[wv]; d = ei[EE + wv]; } else { s = wv - EE; d = s; }
#pragma unroll
    for (int hd = 0; hd < NHEADS; hd++) {
        float alpha = g_ex[wv * NHEADS + hd] / (g_denom[d * NHEADS + hd] + 1e-16f);
        int c = hd * CCH + lane;
        atomicAdd(&g_agg[d * GGDIM + c], alpha * g_xh[s * GGDIM + c]);
    }
}

__global__ void finalize_kernel(const float* __restrict__ bias) {
    int i = blockIdx.x * blockDim.x + threadIdx.x;
    if (i >= NN * GGDIM) return;
    float v = g_agg[i] + bias[i & (GGDIM - 1)];
    g_feat[i] = (v > 0.0f) ? v : (expf(v) - 1.0f);
}

__global__ void head_kernel(const float* __restrict__ Wh, const float* __restrict__ bh,
                            float* __restrict__ out) {
    int n = blockIdx.x * blockDim.x + threadIdx.x;
    if (n >= NN) return;
    float a0 = bh[0], a1 = bh[1];
    const float* f = g_feat + n * GGDIM;
#pragma unroll 8
    for (int k = 0; k < GGDIM; k++) {
        float v = f[k];
        a0 = fmaf(v, Wh[2 * k + 0], a0);
        a1 = fmaf(v, Wh[2 * k + 1], a1);
    }
    out[2 * n + 0] = a0;
    out[2 * n + 1] = a1;
}

// ---------------- launch ------------------------------------------------------
extern "C" void kernel_launch(void* const* d_in, const int* in_sizes, int n_in,
                              void* d_out, int out_size) {
    const float* x_win  = (const float*)d_in[0];
    const int*   ei     = (const int*)  d_in[1];
    const float* Wih    = (const float*)d_in[2];
    const float* Whh    = (const float*)d_in[3];
    const float* bih    = (const float*)d_in[4];
    const float* bhh    = (const float*)d_in[5];
    const float* W1     = (const float*)d_in[6];
    const float* asrc1  = (const float*)d_in[7];
    const float* adst1  = (const float*)d_in[8];
    const float* b1     = (const float*)d_in[9];
    const float* W2     = (const float*)d_in[10];
    const float* asrc2  = (const float*)d_in[11];
    const float* adst2  = (const float*)d_in[12];
    const float* b2     = (const float*)d_in[13];
    const float* Wh     = (const float*)d_in[14];
    const float* bh     = (const float*)d_in[15];
    float* out = (float*)d_out;

    cudaFuncSetAttribute(lstm_all_kernel,
                         cudaFuncAttributeMaxDynamicSharedMemorySize, SMEM_TOTAL);
    lstm_all_kernel<<<LGRID, 256, SMEM_TOTAL>>>(x_win, Wih, Whh, bih, bhh);

    for (int layer = 0; layer < 2; layer++) {
        const float* W    = layer ? W2    : W1;
        const float* asrc = layer ? asrc2 : asrc1;
        const float* adst = layer ? adst2 : adst1;
        const float* bb   = layer ? b2    : b1;

        gemm_xh_kernel<<<NN / 32, 128>>>(W, layer);
        attn_kernel<<<(NN * NHEADS + 255) / 256, 256>>>(asrc, adst);
        fill_kernel<<<2048, 256>>>();
        edge_max_kernel<<<(ETOT + 255) / 256, 256>>>(ei);
        edge_exp_kernel<<<(ETOT + 255) / 256, 256>>>(ei);
        edge_agg_kernel<<<(ETOT * 32 + 255) / 256, 256>>>(ei);
        finalize_kernel<<<(NN * GGDIM + 255) / 256, 256>>>(bb);
    }

    head_kernel<<<(NN + 127) / 128, 128>>>(Wh, bh, out);
}

// round 5
// speedup vs baseline: 8.7274x; 1.7308x over previous
#include <cuda_runtime.h>
#include <cuda_fp16.h>
#include <math.h>
#include <stdint.h>

// ---------------- problem constants ------------------------------------------
#define NN      20000
#define TT      60
#define DDIM    20
#define HH      128
#define GGDIM   128
#define NHEADS  4
#define CCH     32
#define EE      320000
#define ETOT    (EE + NN)
#define G4      512                 // 4*H gate columns
#define LNODES  144                 // nodes per LSTM block (9 m-tiles)
#define MTILES  9
#define LGRID   139                 // 139*144 = 20016 >= 20000, single wave
#define GSTR    (LGRID * LNODES)    // padded node stride (20016)

#define KXP     40                  // A_x/W_x row stride in halves (K=32 + pad)
#define KHP     136                 // A_h row stride in halves (K=128 + pad)
// W_h stored at stride 128 halves (256B) with XOR-16B swizzle (chunk ^= row&7)

// ---------------- LSTM smem layout (bytes) -----------------------------------
#define OFF_WX   0                          // 512 x 40 f16          (40960)
#define OFF_WH   40960                      // 512 x 128 f16 swizzled(131072)
#define OFF_AX   172032                     // 144 x 40 f16          (11520)
#define OFF_AH   183552                     // 144 x 136 f16         (39168)
#define OFF_BIAS 222720                     // 512 f32               (2048)
#define SMEM_TOTAL 224768

// ---------------- scratch (device globals; no allocation allowed) ------------
__device__ float g_h[GSTR * HH];
__device__ float g_xh[NN * GGDIM];
__device__ float g_agg[NN * GGDIM];
__device__ float g_feat[NN * GGDIM];
__device__ float g_asr[NN * NHEADS];
__device__ float g_adt[NN * NHEADS];
__device__ float g_emax[NN * NHEADS];
__device__ float g_denom[NN * NHEADS];
__device__ float g_ex[ETOT * NHEADS];

// ---------------- helpers -----------------------------------------------------
__device__ __forceinline__ float tanhapx(float x) {
    float y; asm("tanh.approx.f32 %0, %1;" : "=f"(y) : "f"(x)); return y;
}
__device__ __forceinline__ float sigt(float x) {
    return fmaf(tanhapx(0.5f * x), 0.5f, 0.5f);
}
__device__ __forceinline__ void mma16816(float* d,
                                         uint32_t a0, uint32_t a1, uint32_t a2, uint32_t a3,
                                         uint32_t b0, uint32_t b1) {
    asm volatile(
        "mma.sync.aligned.m16n8k16.row.col.f32.f16.f16.f32 "
        "{%0,%1,%2,%3}, {%4,%5,%6,%7}, {%8,%9}, {%0,%1,%2,%3};"
        : "+f"(d[0]), "+f"(d[1]), "+f"(d[2]), "+f"(d[3])
        : "r"(a0), "r"(a1), "r"(a2), "r"(a3), "r"(b0), "r"(b1));
}
__device__ __forceinline__ void ldm_x4(uint32_t addr, uint32_t* r) {
    asm volatile("ldmatrix.sync.aligned.m8n8.x4.shared.b16 {%0,%1,%2,%3}, [%4];"
                 : "=r"(r[0]), "=r"(r[1]), "=r"(r[2]), "=r"(r[3]) : "r"(addr));
}

// ---------------- persistent LSTM kernel (all 60 steps, HMMA + ldmatrix) ------
__global__ __launch_bounds__(256, 1) void lstm_all_kernel(
    const float* __restrict__ x,
    const float* __restrict__ Wih, const float* __restrict__ Whh,
    const float* __restrict__ bih, const float* __restrict__ bhh)
{
    extern __shared__ char smem[];
    __half* WX = (__half*)(smem + OFF_WX);
    __half* AX = (__half*)(smem + OFF_AX);
    __half* AH = (__half*)(smem + OFF_AH);
    float*  sbias = (float*)(smem + OFF_BIAS);
    const uint32_t sWX = (uint32_t)__cvta_generic_to_shared(smem + OFF_WX);
    const uint32_t sWH = (uint32_t)__cvta_generic_to_shared(smem + OFF_WH);
    const uint32_t sAX = (uint32_t)__cvta_generic_to_shared(smem + OFF_AX);
    const uint32_t sAH = (uint32_t)__cvta_generic_to_shared(smem + OFF_AH);

    const int tid = threadIdx.x;
    const int blk = blockIdx.x;

    // zero all f16 regions (weights pads, AX pad, AH initial h = 0)
    for (int i = tid; i < OFF_BIAS / 4; i += 256) ((uint32_t*)smem)[i] = 0;
    __syncthreads();

    // ---- stage weights, gate columns permuted: n' = 4*j + gate ----
    for (int i = tid; i < G4 * DDIM; i += 256) {
        int n = i / DDIM, k = i - n * DDIM;
        int row = (n & 3) * HH + (n >> 2);
        WX[n * KXP + k] = __float2half_rn(Wih[row * DDIM + k]);
    }
    for (int i = tid; i < G4 * HH; i += 256) {      // swizzled: chunk ^= (row&7)
        int n = i >> 7, k = i & 127;
        int row = (n & 3) * HH + (n >> 2);
        uint32_t byte = (uint32_t)(n * 256 + ((((k >> 3) ^ (n & 7)) << 4)) + ((k & 7) << 1));
        *(__half*)(smem + OFF_WH + byte) = __float2half_rn(Whh[row * HH + k]);
    }
    for (int i = tid; i < G4; i += 256) {
        int row = (i & 3) * HH + (i >> 2);
        sbias[i] = bih[row] + bhh[row];
    }
    __syncthreads();

    const int wid  = tid >> 5;
    const int lane = tid & 31;
    const int g    = lane >> 2;
    const int cc   = lane & 3;
    const int n0   = wid * 64;               // warp's gate-column base
    const bool odd = (lane & 1);
    const int jbase = (n0 >> 2) + (cc >> 1);

    // per-lane ldmatrix address bases
    const int sub = lane >> 3, rr = lane & 7;
    const int arow = (sub & 1) * 8 + rr;     // A: row offset within 16-row tile
    const int akof = (sub >> 1) * 8;         // A: k offset (0 or 8)
    const int bcol = rr + ((sub >> 1) * 8);  // B: col offset within 16-col pair
    const int bkof = (sub & 1) * 8;          // B: k offset (0 or 8)
    const uint32_t axb = sAX + (uint32_t)(arow * KXP + akof) * 2;
    const uint32_t ahb = sAH + (uint32_t)(arow * KHP + akof) * 2;
    const uint32_t xorv = (uint32_t)(rr << 4);
    uint32_t wxb[4], whb[4];
#pragma unroll
    for (int np = 0; np < 4; ++np) {
        wxb[np] = sWX + (uint32_t)((n0 + np * 16 + bcol) * KXP + bkof) * 2;
        whb[np] = sWH + (uint32_t)(n0 + np * 16 + bcol) * 256;
    }
    const uint32_t bko2 = (uint32_t)(bkof << 1);     // 0 or 16 (chunk offset)

    float bias0[8], bias1[8];
#pragma unroll
    for (int nt = 0; nt < 8; ++nt) {
        bias0[nt] = sbias[n0 + nt * 8 + 2 * cc];
        bias1[nt] = sbias[n0 + nt * 8 + 2 * cc + 1];
    }

    // x-part B fragments: constant across all steps/m-tiles -> registers
    uint32_t bxf[2][4][4];
#pragma unroll
    for (int ks = 0; ks < 2; ++ks)
#pragma unroll
        for (int np = 0; np < 4; ++np)
            ldm_x4(wxb[np] + (uint32_t)(ks * 32), bxf[ks][np]);

    float creg[MTILES][8];
#pragma unroll
    for (int mt = 0; mt < MTILES; ++mt)
#pragma unroll
        for (int nt = 0; nt < 8; ++nt) creg[mt][nt] = 0.0f;

    for (int s = 0; s < TT; ++s) {
        // refill A_x for this timestep
        for (int i = tid; i < LNODES * DDIM; i += 256) {
            int mm = i / DDIM, k = i - mm * DDIM;
            int n = blk * LNODES + mm;
            AX[mm * KXP + k] = __float2half_rn(n < NN ? x[n * (TT * DDIM) + s * DDIM + k] : 0.0f);
        }
        __syncthreads();
        const bool last = (s == TT - 1);

#pragma unroll
        for (int mt = 0; mt < MTILES; ++mt) {
            float acc[8][4];
#pragma unroll
            for (int nt = 0; nt < 8; ++nt) {
                acc[nt][0] = bias0[nt]; acc[nt][1] = bias1[nt];
                acc[nt][2] = bias0[nt]; acc[nt][3] = bias1[nt];
            }
            // ---- x-part GEMM (K=32, B frags in registers) ----
#pragma unroll
            for (int ks = 0; ks < 2; ++ks) {
                uint32_t a[4];
                ldm_x4(axb + (uint32_t)(mt * 16 * (KXP * 2) + ks * 32), a);
#pragma unroll
                for (int np = 0; np < 4; ++np) {
                    mma16816(acc[2 * np],     a[0], a[1], a[2], a[3], bxf[ks][np][0], bxf[ks][np][1]);
                    mma16816(acc[2 * np + 1], a[0], a[1], a[2], a[3], bxf[ks][np][2], bxf[ks][np][3]);
                }
            }
            // ---- h-part GEMM (K=128) ----
#pragma unroll
            for (int ks = 0; ks < 8; ++ks) {
                uint32_t a[4];
                ldm_x4(ahb + (uint32_t)(mt * 16 * (KHP * 2) + ks * 32), a);
#pragma unroll
                for (int np = 0; np < 4; ++np) {
                    uint32_t b[4];
                    ldm_x4(whb[np] + (((uint32_t)(ks * 32) + bko2) ^ xorv), b);
                    mma16816(acc[2 * np],     a[0], a[1], a[2], a[3], b[0], b[1]);
                    mma16816(acc[2 * np + 1], a[0], a[1], a[2], a[3], b[2], b[3]);
                }
            }

            __syncthreads();     // all warps done reading A_h rows of this m-tile

            // ---- epilogue: gates -> c,h ; h_s written into A_h rows of mt ----
#pragma unroll
            for (int nt = 0; nt < 8; ++nt) {
                float c0 = acc[nt][0], c1 = acc[nt][1], c2 = acc[nt][2], c3 = acc[nt][3];
                float x0 = __shfl_xor_sync(0xffffffffu, c0, 1);
                float x1 = __shfl_xor_sync(0xffffffffu, c1, 1);
                float x2 = __shfl_xor_sync(0xffffffffu, c2, 1);
                float x3 = __shfl_xor_sync(0xffffffffu, c3, 1);
                float gi, gf, gg, go; int row;
                if (!odd) { gi = c0; gf = c1; gg = x0; go = x1; row = mt * 16 + g; }
                else      { gi = x2; gf = x3; gg = c2; go = c3; row = mt * 16 + g + 8; }
                int j = jbase + nt * 2;
                float cold = creg[mt][nt];
                float cn = sigt(gf) * cold + sigt(gi) * tanhapx(gg);
                creg[mt][nt] = cn;
                float hv = sigt(go) * tanhapx(cn);
                AH[row * KHP + j] = __float2half_rn(hv);
                if (last) g_h[(blk * LNODES + row) * HH + j] = hv;
            }
        }
        __syncthreads();
    }
}

// ---------------- GAT section (unchanged) -------------------------------------
__device__ __forceinline__ void atomicMaxF(float* addr, float v) {
    v = v + 0.0f;
    if (v >= 0.0f) atomicMax((int*)addr, __float_as_int(v));
    else           atomicMin((unsigned int*)addr, __float_as_uint(v));
}

__global__ __launch_bounds__(128) void gemm_xh_kernel(const float* __restrict__ W, int layer) {
    const float* __restrict__ X = (layer == 0) ? g_h : g_feat;
    __shared__ float sW[32 * GGDIM];
    __shared__ float sA[32 * 32];
    const int tid = threadIdx.x;
    const int n0  = blockIdx.x * 32;

    float acc[32];
#pragma unroll
    for (int r = 0; r < 32; r++) acc[r] = 0.0f;

    for (int k0 = 0; k0 < GGDIM; k0 += 32) {
        __syncthreads();
        for (int i = tid; i < 32 * GGDIM; i += 128) sW[i] = W[k0 * GGDIM + i];
        for (int i = tid; i < 32 * 32; i += 128) {
            int r = i >> 5, kk = i & 31;
            sA[i] = X[(n0 + r) * GGDIM + k0 + kk];
        }
        __syncthreads();
        for (int k = 0; k < 32; k++) {
            float wv = sW[k * GGDIM + tid];
#pragma unroll
            for (int r = 0; r < 32; r++)
                acc[r] = fmaf(sA[r * 32 + k], wv, acc[r]);
        }
    }
#pragma unroll
    for (int r = 0; r < 32; r++) g_xh[(n0 + r) * GGDIM + tid] = acc[r];
}

__global__ void attn_kernel(const float* __restrict__ a_src, const float* __restrict__ a_dst) {
    int i = blockIdx.x * blockDim.x + threadIdx.x;
    if (i >= NN * NHEADS) return;
    int n = i >> 2, hd = i & 3;
    const float* xrow = g_xh + n * GGDIM + hd * CCH;
    float ss = 0.0f, sd = 0.0f;
#pragma unroll
    for (int c = 0; c < CCH; c++) {
        float v = xrow[c];
        ss = fmaf(v, a_src[hd * CCH + c], ss);
        sd = fmaf(v, a_dst[hd * CCH + c], sd);
    }
    g_asr[i] = ss;
    g_adt[i] = sd;
}

__global__ void fill_kernel() {
    int stride = gridDim.x * blockDim.x;
    for (int i = blockIdx.x * blockDim.x + threadIdx.x; i < NN * GGDIM; i += stride)
        g_agg[i] = 0.0f;
    for (int i = blockIdx.x * blockDim.x + threadIdx.x; i < NN * NHEADS; i += stride) {
        g_emax[i]  = -INFINITY;
        g_denom[i] = 0.0f;
    }
}

__global__ void edge_max_kernel(const int* __restrict__ ei) {
    int e = blockIdx.x * blockDim.x + threadIdx.x;
    if (e >= ETOT) return;
    int s, d;
    if (e < EE) { s = ei[e]; d = ei[EE + e]; } else { s = e - EE; d = s; }
#pragma unroll
    for (int hd = 0; hd < NHEADS; hd++) {
        float v = g_asr[s * NHEADS + hd] + g_adt[d * NHEADS + hd];
        v = (v > 0.0f) ? v : 0.2f * v;
        atomicMaxF(&g_emax[d * NHEADS + hd], v);
    }
}

__global__ void edge_exp_kernel(const int* __restrict__ ei) {
    int e = blockIdx.x * blockDim.x + threadIdx.x;
    if (e >= ETOT) return;
    int s, d;
    if (e < EE) { s = ei[e]; d = ei[EE + e]; } else { s = e - EE; d = s; }
#pragma unroll
    for (int hd = 0; hd < NHEADS; hd++) {
        float v = g_asr[s * NHEADS + hd] + g_adt[d * NHEADS + hd];
        v = (v > 0.0f) ? v : 0.2f * v;
        float ex = expf(v - g_emax[d * NHEADS + hd]);
        g_ex[e * NHEADS + hd] = ex;
        atomicAdd(&g_denom[d * NHEADS + hd], ex);
    }
}

__global__ void edge_agg_kernel(const int* __restrict__ ei) {
    int wv   = (blockIdx.x * blockDim.x + threadIdx.x) >> 5;
    int lane = threadIdx.x & 31;
    if (wv >= ETOT) return;
    int s, d;
    if (wv < EE) { s = ei[wv]; d = ei[EE + wv]; } else { s = wv - EE; d = s; }
#pragma unroll
    for (int hd = 0; hd < NHEADS; hd++) {
        float alpha = g_ex[wv * NHEADS + hd] / (g_denom[d * NHEADS + hd] + 1e-16f);
        int c = hd * CCH + lane;
        atomicAdd(&g_agg[d * GGDIM + c], alpha * g_xh[s * GGDIM + c]);
    }
}

__global__ void finalize_kernel(const float* __restrict__ bias) {
    int i = blockIdx.x * blockDim.x + threadIdx.x;
    if (i >= NN * GGDIM) return;
    float v = g_agg[i] + bias[i & (GGDIM - 1)];
    g_feat[i] = (v > 0.0f) ? v : (expf(v) - 1.0f);
}

__global__ void head_kernel(const float* __restrict__ Wh, const float* __restrict__ bh,
                            float* __restrict__ out) {
    int n = blockIdx.x * blockDim.x + threadIdx.x;
    if (n >= NN) return;
    float a0 = bh[0], a1 = bh[1];
    const float* f = g_feat + n * GGDIM;
#pragma unroll 8
    for (int k = 0; k < GGDIM; k++) {
        float v = f[k];
        a0 = fmaf(v, Wh[2 * k + 0], a0);
        a1 = fmaf(v, Wh[2 * k + 1], a1);
    }
    out[2 * n + 0] = a0;
    out[2 * n + 1] = a1;
}

// ---------------- launch ------------------------------------------------------
extern "C" void kernel_launch(void* const* d_in, const int* in_sizes, int n_in,
                              void* d_out, int out_size) {
    const float* x_win  = (const float*)d_in[0];
    const int*   ei     = (const int*)  d_in[1];
    const float* Wih    = (const float*)d_in[2];
    const float* Whh    = (const float*)d_in[3];
    const float* bih    = (const float*)d_in[4];
    const float* bhh    = (const float*)d_in[5];
    const float* W1     = (const float*)d_in[6];
    const float* asrc1  = (const float*)d_in[7];
    const float* adst1  = (const float*)d_in[8];
    const float* b1     = (const float*)d_in[9];
    const float* W2     = (const float*)d_in[10];
    const float* asrc2  = (const float*)d_in[11];
    const float* adst2  = (const float*)d_in[12];
    const float* b2     = (const float*)d_in[13];
    const float* Wh     = (const float*)d_in[14];
    const float* bh     = (const float*)d_in[15];
    float* out = (float*)d_out;

    cudaFuncSetAttribute(lstm_all_kernel,
                         cudaFuncAttributeMaxDynamicSharedMemorySize, SMEM_TOTAL);
    lstm_all_kernel<<<LGRID, 256, SMEM_TOTAL>>>(x_win, Wih, Whh, bih, bhh);

    for (int layer = 0; layer < 2; layer++) {
        const float* W    = layer ? W2    : W1;
        const float* asrc = layer ? asrc2 : asrc1;
        const float* adst = layer ? adst2 : adst1;
        const float* bb   = layer ? b2    : b1;

        gemm_xh_kernel<<<NN / 32, 128>>>(W, layer);
        attn_kernel<<<(NN * NHEADS + 255) / 256, 256>>>(asrc, adst);
        fill_kernel<<<2048, 256>>>();
        edge_max_kernel<<<(ETOT + 255) / 256, 256>>>(ei);
        edge_exp_kernel<<<(ETOT + 255) / 256, 256>>>(ei);
        edge_agg_kernel<<<(ETOT * 32 + 255) / 256, 256>>>(ei);
        finalize_kernel<<<(NN * GGDIM + 255) / 256, 256>>>(bb);
    }

    head_kernel<<<(NN + 127) / 128, 128>>>(Wh, bh, out);
}

// round 6
// speedup vs baseline: 9.6760x; 1.1087x over previous
#include <cuda_runtime.h>
#include <cuda_fp16.h>
#include <math.h>
#include <stdint.h>

// ---------------- problem constants ------------------------------------------
#define NN      20000
#define TT      60
#define DDIM    20
#define HH      128
#define GGDIM   128
#define NHEADS  4
#define CCH     32
#define EE      320000
#define ETOT    (EE + NN)
#define G4      512                 // 4*H gate columns
#define LNODES  144                 // nodes per LSTM block (9 m-tiles)
#define MTILES  9
#define LGRID   139                 // 139*144 = 20016 >= 20000, single wave
#define GSTR    (LGRID * LNODES)

#define KXP     40                  // A_x/W_x row stride in halves (K=32 + pad)
#define KHP     136                 // A_h row stride in halves (K=128 + pad)

// ---------------- LSTM smem layout (bytes) -----------------------------------
#define OFF_WX   0                          // 512 x 40 f16          (40960)
#define OFF_WH   40960                      // 512 x 128 f16 swizzled(131072)
#define OFF_AX   172032                     // 144 x 40 f16          (11520)
#define OFF_AH   183552                     // 144 x 136 f16         (39168)
#define OFF_BIAS 222720                     // 512 f32               (2048)
#define SMEM_TOTAL 224768

// ---------------- scratch (device globals) ------------------------------------
__device__ float g_h[GSTR * HH];
__device__ float g_xh[NN * GGDIM];
__device__ float g_feat[NN * GGDIM];
__device__ float g_asr[NN * NHEADS];
__device__ float g_adt[NN * NHEADS];
__device__ int   g_cnt[NN];
__device__ int   g_row[NN + 1];
__device__ int   g_cur[NN];
__device__ int   g_csr[ETOT];

// ---------------- helpers -----------------------------------------------------
__device__ __forceinline__ float tanhapx(float x) {
    float y; asm("tanh.approx.f32 %0, %1;" : "=f"(y) : "f"(x)); return y;
}
__device__ __forceinline__ float sigt(float x) {
    return fmaf(tanhapx(0.5f * x), 0.5f, 0.5f);
}
__device__ __forceinline__ void mma16816(float* d,
                                         uint32_t a0, uint32_t a1, uint32_t a2, uint32_t a3,
                                         uint32_t b0, uint32_t b1) {
    asm volatile(
        "mma.sync.aligned.m16n8k16.row.col.f32.f16.f16.f32 "
        "{%0,%1,%2,%3}, {%4,%5,%6,%7}, {%8,%9}, {%0,%1,%2,%3};"
        : "+f"(d[0]), "+f"(d[1]), "+f"(d[2]), "+f"(d[3])
        : "r"(a0), "r"(a1), "r"(a2), "r"(a3), "r"(b0), "r"(b1));
}
__device__ __forceinline__ void ldm_x4(uint32_t addr, uint32_t* r) {
    asm volatile("ldmatrix.sync.aligned.m8n8.x4.shared.b16 {%0,%1,%2,%3}, [%4];"
                 : "=r"(r[0]), "=r"(r[1]), "=r"(r[2]), "=r"(r[3]) : "r"(addr));
}
__device__ __forceinline__ float lrelu(float v) { return v > 0.0f ? v : 0.2f * v; }

// ---------------- persistent LSTM kernel (unchanged from R4) ------------------
__global__ __launch_bounds__(256, 1) void lstm_all_kernel(
    const float* __restrict__ x,
    const float* __restrict__ Wih, const float* __restrict__ Whh,
    const float* __restrict__ bih, const float* __restrict__ bhh)
{
    extern __shared__ char smem[];
    __half* WX = (__half*)(smem + OFF_WX);
    __half* AX = (__half*)(smem + OFF_AX);
    __half* AH = (__half*)(smem + OFF_AH);
    float*  sbias = (float*)(smem + OFF_BIAS);
    const uint32_t sWX = (uint32_t)__cvta_generic_to_shared(smem + OFF_WX);
    const uint32_t sWH = (uint32_t)__cvta_generic_to_shared(smem + OFF_WH);
    const uint32_t sAX = (uint32_t)__cvta_generic_to_shared(smem + OFF_AX);
    const uint32_t sAH = (uint32_t)__cvta_generic_to_shared(smem + OFF_AH);

    const int tid = threadIdx.x;
    const int blk = blockIdx.x;

    for (int i = tid; i < OFF_BIAS / 4; i += 256) ((uint32_t*)smem)[i] = 0;
    __syncthreads();

    for (int i = tid; i < G4 * DDIM; i += 256) {
        int n = i / DDIM, k = i - n * DDIM;
        int row = (n & 3) * HH + (n >> 2);
        WX[n * KXP + k] = __float2half_rn(Wih[row * DDIM + k]);
    }
    for (int i = tid; i < G4 * HH; i += 256) {
        int n = i >> 7, k = i & 127;
        int row = (n & 3) * HH + (n >> 2);
        uint32_t byte = (uint32_t)(n * 256 + ((((k >> 3) ^ (n & 7)) << 4)) + ((k & 7) << 1));
        *(__half*)(smem + OFF_WH + byte) = __float2half_rn(Whh[row * HH + k]);
    }
    for (int i = tid; i < G4; i += 256) {
        int row = (i & 3) * HH + (i >> 2);
        sbias[i] = bih[row] + bhh[row];
    }
    __syncthreads();

    const int wid  = tid >> 5;
    const int lane = tid & 31;
    const int g    = lane >> 2;
    const int cc   = lane & 3;
    const int n0   = wid * 64;
    const bool odd = (lane & 1);
    const int jbase = (n0 >> 2) + (cc >> 1);

    const int sub = lane >> 3, rr = lane & 7;
    const int arow = (sub & 1) * 8 + rr;
    const int akof = (sub >> 1) * 8;
    const int bcol = rr + ((sub >> 1) * 8);
    const int bkof = (sub & 1) * 8;
    const uint32_t axb = sAX + (uint32_t)(arow * KXP + akof) * 2;
    const uint32_t ahb = sAH + (uint32_t)(arow * KHP + akof) * 2;
    const uint32_t xorv = (uint32_t)(rr << 4);
    uint32_t wxb[4], whb[4];
#pragma unroll
    for (int np = 0; np < 4; ++np) {
        wxb[np] = sWX + (uint32_t)((n0 + np * 16 + bcol) * KXP + bkof) * 2;
        whb[np] = sWH + (uint32_t)(n0 + np * 16 + bcol) * 256;
    }
    const uint32_t bko2 = (uint32_t)(bkof << 1);

    float bias0[8], bias1[8];
#pragma unroll
    for (int nt = 0; nt < 8; ++nt) {
        bias0[nt] = sbias[n0 + nt * 8 + 2 * cc];
        bias1[nt] = sbias[n0 + nt * 8 + 2 * cc + 1];
    }

    uint32_t bxf[2][4][4];
#pragma unroll
    for (int ks = 0; ks < 2; ++ks)
#pragma unroll
        for (int np = 0; np < 4; ++np)
            ldm_x4(wxb[np] + (uint32_t)(ks * 32), bxf[ks][np]);

    float creg[MTILES][8];
#pragma unroll
    for (int mt = 0; mt < MTILES; ++mt)
#pragma unroll
        for (int nt = 0; nt < 8; ++nt) creg[mt][nt] = 0.0f;

    for (int s = 0; s < TT; ++s) {
        for (int i = tid; i < LNODES * DDIM; i += 256) {
            int mm = i / DDIM, k = i - mm * DDIM;
            int n = blk * LNODES + mm;
            AX[mm * KXP + k] = __float2half_rn(n < NN ? x[n * (TT * DDIM) + s * DDIM + k] : 0.0f);
        }
        __syncthreads();
        const bool last = (s == TT - 1);

#pragma unroll
        for (int mt = 0; mt < MTILES; ++mt) {
            float acc[8][4];
#pragma unroll
            for (int nt = 0; nt < 8; ++nt) {
                acc[nt][0] = bias0[nt]; acc[nt][1] = bias1[nt];
                acc[nt][2] = bias0[nt]; acc[nt][3] = bias1[nt];
            }
#pragma unroll
            for (int ks = 0; ks < 2; ++ks) {
                uint32_t a[4];
                ldm_x4(axb + (uint32_t)(mt * 16 * (KXP * 2) + ks * 32), a);
#pragma unroll
                for (int np = 0; np < 4; ++np) {
                    mma16816(acc[2 * np],     a[0], a[1], a[2], a[3], bxf[ks][np][0], bxf[ks][np][1]);
                    mma16816(acc[2 * np + 1], a[0], a[1], a[2], a[3], bxf[ks][np][2], bxf[ks][np][3]);
                }
            }
#pragma unroll
            for (int ks = 0; ks < 8; ++ks) {
                uint32_t a[4];
                ldm_x4(ahb + (uint32_t)(mt * 16 * (KHP * 2) + ks * 32), a);
#pragma unroll
                for (int np = 0; np < 4; ++np) {
                    uint32_t b[4];
                    ldm_x4(whb[np] + (((uint32_t)(ks * 32) + bko2) ^ xorv), b);
                    mma16816(acc[2 * np],     a[0], a[1], a[2], a[3], b[0], b[1]);
                    mma16816(acc[2 * np + 1], a[0], a[1], a[2], a[3], b[2], b[3]);
                }
            }

            __syncthreads();

#pragma unroll
            for (int nt = 0; nt < 8; ++nt) {
                float c0 = acc[nt][0], c1 = acc[nt][1], c2 = acc[nt][2], c3 = acc[nt][3];
                float x0 = __shfl_xor_sync(0xffffffffu, c0, 1);
                float x1 = __shfl_xor_sync(0xffffffffu, c1, 1);
                float x2 = __shfl_xor_sync(0xffffffffu, c2, 1);
                float x3 = __shfl_xor_sync(0xffffffffu, c3, 1);
                float gi, gf, gg, go; int row;
                if (!odd) { gi = c0; gf = c1; gg = x0; go = x1; row = mt * 16 + g; }
                else      { gi = x2; gf = x3; gg = c2; go = c3; row = mt * 16 + g + 8; }
                int j = jbase + nt * 2;
                float cold = creg[mt][nt];
                float cn = sigt(gf) * cold + sigt(gi) * tanhapx(gg);
                creg[mt][nt] = cn;
                float hv = sigt(go) * tanhapx(cn);
                AH[row * KHP + j] = __float2half_rn(hv);
                if (last) g_h[(blk * LNODES + row) * HH + j] = hv;
            }
        }
        __syncthreads();
    }
}

// ---------------- CSR build ----------------------------------------------------
__global__ void csr_zero_kernel() {
    int i = blockIdx.x * blockDim.x + threadIdx.x;
    if (i < NN) g_cnt[i] = 0;
}
__global__ void csr_count_kernel(const int* __restrict__ ei) {
    int e = blockIdx.x * blockDim.x + threadIdx.x;
    if (e >= ETOT) return;
    int d = (e < EE) ? ei[EE + e] : (e - EE);
    atomicAdd(&g_cnt[d], 1);
}
__global__ void csr_scan_kernel() {          // single block, 256 threads
    __shared__ int spart[256];
    const int t = threadIdx.x;
    const int ITEMS = (NN + 255) / 256;      // 79
    int base = t * ITEMS;
    int sum = 0;
    for (int i = 0; i < ITEMS; ++i) {
        int idx = base + i;
        if (idx < NN) sum += g_cnt[idx];
    }
    spart[t] = sum;
    __syncthreads();
    for (int off = 1; off < 256; off <<= 1) {
        int v = 0;
        if (t >= off) v = spart[t - off];
        __syncthreads();
        if (t >= off) spart[t] += v;
        __syncthreads();
    }
    int run = (t == 0) ? 0 : spart[t - 1];
    for (int i = 0; i < ITEMS; ++i) {
        int idx = base + i;
        if (idx < NN) {
            g_row[idx] = run;
            g_cur[idx] = run;
            run += g_cnt[idx];
        }
    }
    if (t == 255) g_row[NN] = spart[255];
}
__global__ void csr_scatter_kernel(const int* __restrict__ ei) {
    int e = blockIdx.x * blockDim.x + threadIdx.x;
    if (e >= ETOT) return;
    int s, d;
    if (e < EE) { s = ei[e]; d = ei[EE + e]; } else { s = e - EE; d = s; }
    int pos = atomicAdd(&g_cur[d], 1);
    g_csr[pos] = s;
}

// ---------------- GAT: xh = X @ W ---------------------------------------------
__global__ __launch_bounds__(128) void gemm_xh_kernel(const float* __restrict__ W, int layer) {
    const float* __restrict__ X = (layer == 0) ? g_h : g_feat;
    __shared__ float sW[32 * GGDIM];
    __shared__ float sA[32 * 32];
    const int tid = threadIdx.x;
    const int n0  = blockIdx.x * 32;

    float acc[32];
#pragma unroll
    for (int r = 0; r < 32; r++) acc[r] = 0.0f;

    for (int k0 = 0; k0 < GGDIM; k0 += 32) {
        __syncthreads();
        for (int i = tid; i < 32 * GGDIM; i += 128) sW[i] = W[k0 * GGDIM + i];
        for (int i = tid; i < 32 * 32; i += 128) {
            int r = i >> 5, kk = i & 31;
            sA[i] = X[(n0 + r) * GGDIM + k0 + kk];
        }
        __syncthreads();
        for (int k = 0; k < 32; k++) {
            float wv = sW[k * GGDIM + tid];
#pragma unroll
            for (int r = 0; r < 32; r++)
                acc[r] = fmaf(sA[r * 32 + k], wv, acc[r]);
        }
    }
#pragma unroll
    for (int r = 0; r < 32; r++) g_xh[(n0 + r) * GGDIM + tid] = acc[r];
}

__global__ void attn_kernel(const float* __restrict__ a_src, const float* __restrict__ a_dst) {
    int i = blockIdx.x * blockDim.x + threadIdx.x;
    if (i >= NN * NHEADS) return;
    int n = i >> 2, hd = i & 3;
    const float* xrow = g_xh + n * GGDIM + hd * CCH;
    float ss = 0.0f, sd = 0.0f;
#pragma unroll
    for (int c = 0; c < CCH; c++) {
        float v = xrow[c];
        ss = fmaf(v, a_src[hd * CCH + c], ss);
        sd = fmaf(v, a_dst[hd * CCH + c], sd);
    }
    g_asr[i] = ss;
    g_adt[i] = sd;
}

// ---------------- fused softmax + aggregate + bias + ELU (warp per dst) -------
__global__ __launch_bounds__(256) void gat_agg_kernel(const float* __restrict__ bias) {
    const int d    = (blockIdx.x * 256 + threadIdx.x) >> 5;
    const int lane = threadIdx.x & 31;
    if (d >= NN) return;
    const int start = g_row[d], end = g_row[d + 1];

    const float4 adt4 = *(const float4*)&g_adt[d * 4];

    // phase A: lanes parallel over edges, per-head exp-sums
    float s0 = 0.0f, s1 = 0.0f, s2 = 0.0f, s3 = 0.0f;
    for (int idx = start + lane; idx < end; idx += 32) {
        int s = g_csr[idx];
        float4 a = *(const float4*)&g_asr[s * 4];
        s0 += expf(lrelu(a.x + adt4.x));
        s1 += expf(lrelu(a.y + adt4.y));
        s2 += expf(lrelu(a.z + adt4.z));
        s3 += expf(lrelu(a.w + adt4.w));
    }
#pragma unroll
    for (int off = 16; off > 0; off >>= 1) {
        s0 += __shfl_xor_sync(0xffffffffu, s0, off);
        s1 += __shfl_xor_sync(0xffffffffu, s1, off);
        s2 += __shfl_xor_sync(0xffffffffu, s2, off);
        s3 += __shfl_xor_sync(0xffffffffu, s3, off);
    }

    const int head = lane >> 3;               // lane handles channels lane*4..+3
    float adt_h, den_h;
    if (head == 0)      { adt_h = adt4.x; den_h = s0; }
    else if (head == 1) { adt_h = adt4.y; den_h = s1; }
    else if (head == 2) { adt_h = adt4.z; den_h = s2; }
    else                { adt_h = adt4.w; den_h = s3; }
    const float inv_den = 1.0f / (den_h + 1e-16f);

    // phase B: sequential edges, lanes split 128 channels
    float4 acc = make_float4(0.0f, 0.0f, 0.0f, 0.0f);
    for (int idx = start; idx < end; ++idx) {
        int s = g_csr[idx];                                  // broadcast
        float as_h = g_asr[s * 4 + head];                    // 8-lane broadcast
        float alpha = expf(lrelu(as_h + adt_h)) * inv_den;
        float4 xv = *(const float4*)&g_xh[s * GGDIM + lane * 4];
        acc.x = fmaf(alpha, xv.x, acc.x);
        acc.y = fmaf(alpha, xv.y, acc.y);
        acc.z = fmaf(alpha, xv.z, acc.z);
        acc.w = fmaf(alpha, xv.w, acc.w);
    }

    const float4 bv = *(const float4*)&bias[lane * 4];
    float4 out;
    float v;
    v = acc.x + bv.x; out.x = v > 0.0f ? v : (expf(v) - 1.0f);
    v = acc.y + bv.y; out.y = v > 0.0f ? v : (expf(v) - 1.0f);
    v = acc.z + bv.z; out.z = v > 0.0f ? v : (expf(v) - 1.0f);
    v = acc.w + bv.w; out.w = v > 0.0f ? v : (expf(v) - 1.0f);
    *(float4*)&g_feat[d * GGDIM + lane * 4] = out;
}

// ---------------- linear head --------------------------------------------------
__global__ void head_kernel(const float* __restrict__ Wh, const float* __restrict__ bh,
                            float* __restrict__ out) {
    int n = blockIdx.x * blockDim.x + threadIdx.x;
    if (n >= NN) return;
    float a0 = bh[0], a1 = bh[1];
    const float* f = g_feat + n * GGDIM;
#pragma unroll 8
    for (int k = 0; k < GGDIM; k++) {
        float v = f[k];
        a0 = fmaf(v, Wh[2 * k + 0], a0);
        a1 = fmaf(v, Wh[2 * k + 1], a1);
    }
    out[2 * n + 0] = a0;
    out[2 * n + 1] = a1;
}

// ---------------- launch --------------------------------------------------------
extern "C" void kernel_launch(void* const* d_in, const int* in_sizes, int n_in,
                              void* d_out, int out_size) {
    const float* x_win  = (const float*)d_in[0];
    const int*   ei     = (const int*)  d_in[1];
    const float* Wih    = (const float*)d_in[2];
    const float* Whh    = (const float*)d_in[3];
    const float* bih    = (const float*)d_in[4];
    const float* bhh    = (const float*)d_in[5];
    const float* W1     = (const float*)d_in[6];
    const float* asrc1  = (const float*)d_in[7];
    const float* adst1  = (const float*)d_in[8];
    const float* b1     = (const float*)d_in[9];
    const float* W2     = (const float*)d_in[10];
    const float* asrc2  = (const float*)d_in[11];
    const float* adst2  = (const float*)d_in[12];
    const float* b2     = (const float*)d_in[13];
    const float* Wh     = (const float*)d_in[14];
    const float* bh     = (const float*)d_in[15];
    float* out = (float*)d_out;

    cudaFuncSetAttribute(lstm_all_kernel,
                         cudaFuncAttributeMaxDynamicSharedMemorySize, SMEM_TOTAL);
    lstm_all_kernel<<<LGRID, 256, SMEM_TOTAL>>>(x_win, Wih, Whh, bih, bhh);

    // CSR build (overlaps LSTM on the same stream queue; shared by both layers)
    csr_zero_kernel<<<(NN + 255) / 256, 256>>>();
    csr_count_kernel<<<(ETOT + 255) / 256, 256>>>(ei);
    csr_scan_kernel<<<1, 256>>>();
    csr_scatter_kernel<<<(ETOT + 255) / 256, 256>>>(ei);

    for (int layer = 0; layer < 2; layer++) {
        const float* W    = layer ? W2    : W1;
        const float* asrc = layer ? asrc2 : asrc1;
        const float* adst = layer ? adst2 : adst1;
        const float* bb   = layer ? b2    : b1;

        gemm_xh_kernel<<<NN / 32, 128>>>(W, layer);
        attn_kernel<<<(NN * NHEADS + 255) / 256, 256>>>(asrc, adst);
        gat_agg_kernel<<<(NN * 32 + 255) / 256, 256>>>(bb);
    }

    head_kernel<<<(NN + 127) / 128, 128>>>(Wh, bh, out);
}